// round 16
// baseline (speedup 1.0000x reference)
#include <cuda_runtime.h>
#include <cuda_fp16.h>
#include <mma.h>
#include <math.h>
#include <float.h>
#include <stdint.h>
#include <type_traits>

using namespace nvcuda;

#define NROWS 8192
#define DIN   1024
#define DD    512
#define DD2   1024     // combined eh|et width
#define DH    256      // D/2
#define TK    6
#define NTILE 64       // NROWS/128 column tiles in logits GEMM
#define NCAND (NTILE * TK)   // 384 candidates per row
#define NCHUNK 128
#define ROWS_PER_CHUNK (NROWS / NCHUNK)
#define LN_EPS 1e-5f
#define SCALE_LOGITS 0.044194173824159216f  // 512^-0.5

// ------------------------- scratch (device globals; no cudaMalloc allowed) ---
__device__ float  g_cand_v[NROWS * NCAND];  // 12.6 MB
__device__ int    g_cand_i[NROWS * NCAND];
__device__ float  g_tw[NROWS * TK];
__device__ int    g_ti[NROWS * TK];
__device__ float  g_emb[NROWS * DD];
__device__ float  g_hatt[NROWS * DH];
__device__ float  g_att[NROWS];
__device__ float  g_a[NROWS];
__device__ float  g_part[NCHUNK * DD];
__device__ float  g_colmean[DD];
// fp16 operand buffers
__device__ __half g_xh[NROWS * DIN];
__device__ __half g_h16[NROWS * DD];
__device__ __half g_ehet16[NROWS * DD2];   // eh | et combined, 16 MB
__device__ __half g_s1h[NROWS * DD];
__device__ __half g_b1h[NROWS * DD];
__device__ __half g_emb16[NROWS * DD];
// fp16 weights
__device__ __half g_fc1_wh[DIN * DD];
__device__ __half g_whwt[DD * DD2];        // wh | wt packed [512, 1024]
__device__ __half g_lin1_wh[DD * DD];
__device__ __half g_lin2_wh[DD * DD];
__device__ __half g_att1_wh[DD * DH];
__device__ float  g_bias2[DD2];            // wh_b | wt_b

// ------------------------- cp.async helpers ----------------------------------
__device__ __forceinline__ void cp_async16(void* smem_ptr, const void* gptr) {
    unsigned saddr = (unsigned)__cvta_generic_to_shared(smem_ptr);
    asm volatile("cp.async.cg.shared.global [%0], [%1], 16;\n" :: "r"(saddr), "l"(gptr));
}
__device__ __forceinline__ void cp_commit() { asm volatile("cp.async.commit_group;\n"); }
__device__ __forceinline__ void cp_wait0()  { asm volatile("cp.async.wait_group 0;\n"); }

// ------------------------- fp16 wmma GEMM: BK=64, 2-stage, occ-2 --------------
#define LDA   72      // halves: 64 + 8 pad
#define LDBN  136     // halves: 128 + 8 pad
#define LDC   68      // floats
#define LDP   136     // halves (dual-kernel stash)
#define A_H   (128 * LDA)                    // 9216 halves
#define B_H   9216
#define STAGE_H (A_H + B_H)                   // 18432 halves = 36864 B
#define SMEM_BYTES (2 * STAGE_H * 2)          // 73728 B -> 2 CTAs/SM
#define DUAL_SMEM (SMEM_BYTES + 128 * LDP * 2)  // 108544 B

template <bool NT>
__device__ __forceinline__ void load_tiles(__half* As, __half* Bs,
                                           const __half* __restrict__ A,
                                           const __half* __restrict__ B,
                                           int m0, int n0, int k0,
                                           int lda, int ldb, int tid) {
    #pragma unroll
    for (int f = tid; f < 1024; f += 256) {
        int m = f >> 3, kq = (f & 7) << 3;
        cp_async16(&As[m * LDA + kq], &A[(size_t)(m0 + m) * lda + k0 + kq]);
    }
    if (NT) {
        #pragma unroll
        for (int f = tid; f < 1024; f += 256) {
            int n = f >> 3, kq = (f & 7) << 3;
            cp_async16(&Bs[n * LDA + kq], &B[(size_t)(n0 + n) * ldb + k0 + kq]);
        }
    } else {
        #pragma unroll
        for (int f = tid; f < 1024; f += 256) {
            int k = f >> 4, nq = (f & 15) << 3;
            cp_async16(&Bs[k * LDBN + nq], &B[(size_t)(k0 + k) * ldb + n0 + nq]);
        }
    }
}

template <bool NT>
__device__ __forceinline__ void gemm_mainloop(
        __half* smem, const __half* __restrict__ A, const __half* __restrict__ B,
        wmma::fragment<wmma::accumulator, 16, 16, 16, float> (&acc)[2][4],
        int m0, int n0, int K, int lda, int ldb, int tid, int m_off, int n_off) {
    using BLayout = typename std::conditional<NT, wmma::col_major, wmma::row_major>::type;
    const int NC = K / 64;
    load_tiles<NT>(smem, smem + A_H, A, B, m0, n0, 0, lda, ldb, tid);
    cp_commit();
    for (int i = 0; i < NC; i++) {
        cp_wait0();
        __syncthreads();
        __half* As = smem + (i & 1) * STAGE_H;
        __half* Bs = As + A_H;
        if (i + 1 < NC) {
            __half* An = smem + ((i + 1) & 1) * STAGE_H;
            load_tiles<NT>(An, An + A_H, A, B, m0, n0, (i + 1) * 64, lda, ldb, tid);
            cp_commit();
        }
        #pragma unroll
        for (int kk = 0; kk < 4; kk++) {
            wmma::fragment<wmma::matrix_a, 16, 16, 16, __half, wmma::row_major> af[2];
            wmma::fragment<wmma::matrix_b, 16, 16, 16, __half, BLayout> bf[4];
            #pragma unroll
            for (int i2 = 0; i2 < 2; i2++)
                wmma::load_matrix_sync(af[i2], &As[(m_off + i2 * 16) * LDA + kk * 16], LDA);
            #pragma unroll
            for (int j = 0; j < 4; j++) {
                if (NT)
                    wmma::load_matrix_sync(bf[j], &Bs[(n_off + j * 16) * LDA + kk * 16], LDA);
                else
                    wmma::load_matrix_sync(bf[j], &Bs[kk * 16 * LDBN + n_off + j * 16], LDBN);
            }
            #pragma unroll
            for (int i2 = 0; i2 < 2; i2++)
                #pragma unroll
                for (int j = 0; j < 4; j++)
                    wmma::mma_sync(acc[i2][j], af[i2], bf[j], acc[i2][j]);
        }
    }
}

// TOPK=false: standard epilogue to C32/C16.  TOPK=true: per-tile top-6 candidates.
template <int EPI, bool NT, bool ACC, bool TOPK>
__global__ __launch_bounds__(256, 2)
void gemm16_kernel(const __half* __restrict__ A, const __half* __restrict__ B,
                   const float* __restrict__ bias, float* __restrict__ C32,
                   __half* __restrict__ C16, int M, int Nc, int K,
                   int lda, int ldb, float alpha,
                   float* __restrict__ cand_v, int* __restrict__ cand_i) {
    extern __shared__ __half smem[];
    const int tid    = threadIdx.x;
    const int warpId = tid >> 5;
    const int m_off  = (warpId >> 1) * 32;
    const int n_off  = (warpId & 1) * 64;
    const int warp_n = warpId & 1;
    const int m0 = blockIdx.y * 128;
    const int n0 = blockIdx.x * 128;

    wmma::fragment<wmma::accumulator, 16, 16, 16, float> acc[2][4];
    #pragma unroll
    for (int i = 0; i < 2; i++)
        #pragma unroll
        for (int j = 0; j < 4; j++)
            wmma::fill_fragment(acc[i][j], 0.0f);

    gemm_mainloop<NT>(smem, A, B, acc, m0, n0, K, lda, ldb, tid, m_off, n_off);

    float* Cs = (float*)smem;

    float tv[TK]; int tix[TK];
    if (TOPK) {
        #pragma unroll
        for (int k = 0; k < TK; k++) { tv[k] = -FLT_MAX; tix[k] = 0x7FFFFFFF; }
    }

    #pragma unroll
    for (int h = 0; h < 2; h++) {
        __syncthreads();
        if (warp_n == h) {
            #pragma unroll
            for (int i = 0; i < 2; i++)
                #pragma unroll
                for (int j = 0; j < 4; j++)
                    wmma::store_matrix_sync(&Cs[(m_off + i * 16) * LDC + j * 16],
                                            acc[i][j], LDC, wmma::mem_row_major);
        }
        __syncthreads();
        if (TOPK) {
            // thread t: row t>>1, scans 32 cols of this 64-wide chunk (ascending)
            int r = tid >> 1, half = tid & 1;
            #pragma unroll 8
            for (int cc = 0; cc < 32; cc++) {
                int c = half * 32 + cc;
                float v = Cs[r * LDC + c] * alpha;
                if (v > tv[TK - 1]) {
                    int n = n0 + h * 64 + c;
                    int pos = TK - 1;
                    #pragma unroll
                    for (int k = TK - 2; k >= 0; k--) {
                        if (v > tv[k]) { tv[k + 1] = tv[k]; tix[k + 1] = tix[k]; pos = k; }
                    }
                    tv[pos] = v; tix[pos] = n;
                }
            }
        } else {
            #pragma unroll
            for (int e = tid; e < 1024; e += 256) {
                int m = e >> 3, c8 = (e & 7) << 3;
                int n = n0 + h * 64 + c8;
                float4 v0 = *reinterpret_cast<const float4*>(&Cs[m * LDC + c8]);
                float4 v1 = *reinterpret_cast<const float4*>(&Cs[m * LDC + c8 + 4]);
                float v[8] = {v0.x, v0.y, v0.z, v0.w, v1.x, v1.y, v1.z, v1.w};
                size_t o = (size_t)(m0 + m) * Nc + n;
                float acc32[8];
                if (ACC) {
                    float4 a0 = *reinterpret_cast<const float4*>(&C32[o]);
                    float4 a1 = *reinterpret_cast<const float4*>(&C32[o + 4]);
                    acc32[0] = a0.x; acc32[1] = a0.y; acc32[2] = a0.z; acc32[3] = a0.w;
                    acc32[4] = a1.x; acc32[5] = a1.y; acc32[6] = a1.z; acc32[7] = a1.w;
                }
                #pragma unroll
                for (int q = 0; q < 8; q++) {
                    float t = v[q] * alpha;
                    if (bias) t += bias[n + q];
                    if (EPI == 1) t = fmaxf(t, 0.0f);
                    else if (EPI == 2) t = (t > 0.0f) ? t : 0.01f * t;
                    if (ACC) t += acc32[q];
                    v[q] = t;
                }
                if (C32) {
                    *reinterpret_cast<float4*>(&C32[o])     = make_float4(v[0], v[1], v[2], v[3]);
                    *reinterpret_cast<float4*>(&C32[o + 4]) = make_float4(v[4], v[5], v[6], v[7]);
                }
                if (C16) {
                    __half2 h0 = __floats2half2_rn(v[0], v[1]);
                    __half2 h1 = __floats2half2_rn(v[2], v[3]);
                    __half2 h2 = __floats2half2_rn(v[4], v[5]);
                    __half2 h3 = __floats2half2_rn(v[6], v[7]);
                    uint4 pkt;
                    pkt.x = *reinterpret_cast<uint32_t*>(&h0);
                    pkt.y = *reinterpret_cast<uint32_t*>(&h1);
                    pkt.z = *reinterpret_cast<uint32_t*>(&h2);
                    pkt.w = *reinterpret_cast<uint32_t*>(&h3);
                    *reinterpret_cast<uint4*>(&C16[o]) = pkt;
                }
            }
        }
    }

    if (TOPK) {
        // merge the 2 half-row lists through spare smem (beyond Cs: 34816 B used)
        __syncthreads();
        float* sv = (float*)((char*)smem + 35840);          // 256*6 floats
        int*   si = (int*)(sv + 256 * TK);                  // 256*6 ints
        #pragma unroll
        for (int k = 0; k < TK; k++) { sv[tid * TK + k] = tv[k]; si[tid * TK + k] = tix[k]; }
        __syncthreads();
        if ((tid & 1) == 0) {
            int r = tid >> 1;
            const float* bvv = &sv[(tid + 1) * TK];
            const int*   bii = &si[(tid + 1) * TK];
            float rv[TK]; int ri[TK];
            int ia = 0, ib = 0;
            #pragma unroll
            for (int k = 0; k < TK; k++) {
                float va = tv[ia], vb = bvv[ib];
                bool takeA = (va > vb) || (va == vb && tix[ia] <= bii[ib]);
                if (takeA) { rv[k] = va; ri[k] = tix[ia]; ia++; }
                else       { rv[k] = vb; ri[k] = bii[ib]; ib++; }
            }
            size_t base = (size_t)(m0 + r) * NCAND + blockIdx.x * TK;
            #pragma unroll
            for (int k = 0; k < TK; k++) { cand_v[base + k] = rv[k]; cand_i[base + k] = ri[k]; }
        }
    }
}

// ------------------------- candidate reduce: 384 -> top-6 per row ------------
__global__ void topk_reduce_kernel(const float* __restrict__ cand_v,
                                   const int* __restrict__ cand_i,
                                   float* __restrict__ tw, int* __restrict__ ti) {
    const unsigned FULL = 0xFFFFFFFFu;
    int warp = threadIdx.x >> 5;
    int lane = threadIdx.x & 31;
    int row = blockIdx.x * 8 + warp;
    const float* cv = cand_v + (size_t)row * NCAND;
    const int*   ci = cand_i + (size_t)row * NCAND;

    float val[TK]; int idx[TK];
    #pragma unroll
    for (int k = 0; k < TK; k++) { val[k] = -FLT_MAX; idx[k] = 0x7FFFFFFF; }

    #pragma unroll
    for (int j = 0; j < NCAND / 32; j++) {
        int p = lane + j * 32;
        float v = cv[p]; int ii = ci[p];
        if (v > val[TK - 1] || (v == val[TK - 1] && ii < idx[TK - 1])) {
            int pos = TK - 1;
            #pragma unroll
            for (int k = TK - 2; k >= 0; k--) {
                if (v > val[k] || (v == val[k] && ii < idx[k])) {
                    val[k + 1] = val[k]; idx[k + 1] = idx[k]; pos = k;
                }
            }
            val[pos] = v; idx[pos] = ii;
        }
    }

    int head = 0;
    for (int r = 0; r < TK; r++) {
        float bv = (head < TK) ? val[head] : -FLT_MAX;
        int   bi = (head < TK) ? idx[head] : 0x7FFFFFFF;
        int   bl = lane;
        #pragma unroll
        for (int off = 16; off > 0; off >>= 1) {
            float ov = __shfl_down_sync(FULL, bv, off);
            int   oi = __shfl_down_sync(FULL, bi, off);
            int   ol = __shfl_down_sync(FULL, bl, off);
            if (ov > bv || (ov == bv && oi < bi)) { bv = ov; bi = oi; bl = ol; }
        }
        bv = __shfl_sync(FULL, bv, 0);
        bi = __shfl_sync(FULL, bi, 0);
        bl = __shfl_sync(FULL, bl, 0);
        if (lane == 0) { tw[row * TK + r] = bv; ti[row * TK + r] = bi; }
        if (lane == bl) head++;
    }
}

// ---------- fused dual GEMM: emb = leaky(A1@B1+b1) + leaky(A2@B2+b2) ----------
__global__ __launch_bounds__(256, 2)
void gemm_dual_kernel(const __half* __restrict__ A1, const __half* __restrict__ B1,
                      const float* __restrict__ bias1,
                      const __half* __restrict__ A2, const __half* __restrict__ B2,
                      const float* __restrict__ bias2,
                      float* __restrict__ C32, __half* __restrict__ C16,
                      int M, int Nc, int K) {
    extern __shared__ __half smem[];
    __half* P = smem + 2 * STAGE_H;
    const int tid    = threadIdx.x;
    const int warpId = tid >> 5;
    const int m_off  = (warpId >> 1) * 32;
    const int n_off  = (warpId & 1) * 64;
    const int warp_n = warpId & 1;
    const int m0 = blockIdx.y * 128;
    const int n0 = blockIdx.x * 128;

    float* Cs = (float*)smem;

    #pragma unroll
    for (int pass = 0; pass < 2; pass++) {
        const __half* A = pass ? A2 : A1;
        const __half* B = pass ? B2 : B1;
        const float* bias = pass ? bias2 : bias1;

        wmma::fragment<wmma::accumulator, 16, 16, 16, float> acc[2][4];
        #pragma unroll
        for (int i = 0; i < 2; i++)
            #pragma unroll
            for (int j = 0; j < 4; j++)
                wmma::fill_fragment(acc[i][j], 0.0f);

        __syncthreads();
        gemm_mainloop<false>(smem, A, B, acc, m0, n0, K, Nc, Nc, tid, m_off, n_off);

        #pragma unroll
        for (int h = 0; h < 2; h++) {
            __syncthreads();
            if (warp_n == h) {
                #pragma unroll
                for (int i = 0; i < 2; i++)
                    #pragma unroll
                    for (int j = 0; j < 4; j++)
                        wmma::store_matrix_sync(&Cs[(m_off + i * 16) * LDC + j * 16],
                                                acc[i][j], LDC, wmma::mem_row_major);
            }
            __syncthreads();
            #pragma unroll
            for (int e = tid; e < 1024; e += 256) {
                int m = e >> 3, c8 = (e & 7) << 3;
                int n = n0 + h * 64 + c8;
                int pc = h * 64 + c8;
                float4 v0 = *reinterpret_cast<const float4*>(&Cs[m * LDC + c8]);
                float4 v1 = *reinterpret_cast<const float4*>(&Cs[m * LDC + c8 + 4]);
                float v[8] = {v0.x, v0.y, v0.z, v0.w, v1.x, v1.y, v1.z, v1.w};
                #pragma unroll
                for (int q = 0; q < 8; q++) {
                    float t = v[q] + bias[n + q];
                    v[q] = (t > 0.0f) ? t : 0.01f * t;
                }
                if (pass == 0) {
                    __half2 h0 = __floats2half2_rn(v[0], v[1]);
                    __half2 h1 = __floats2half2_rn(v[2], v[3]);
                    __half2 h2 = __floats2half2_rn(v[4], v[5]);
                    __half2 h3 = __floats2half2_rn(v[6], v[7]);
                    uint4 pkt;
                    pkt.x = *reinterpret_cast<uint32_t*>(&h0);
                    pkt.y = *reinterpret_cast<uint32_t*>(&h1);
                    pkt.z = *reinterpret_cast<uint32_t*>(&h2);
                    pkt.w = *reinterpret_cast<uint32_t*>(&h3);
                    *reinterpret_cast<uint4*>(&P[m * LDP + pc]) = pkt;
                } else {
                    uint4 pkt = *reinterpret_cast<const uint4*>(&P[m * LDP + pc]);
                    const __half* hp = reinterpret_cast<const __half*>(&pkt);
                    #pragma unroll
                    for (int q = 0; q < 8; q++) v[q] += __half2float(hp[q]);
                    size_t o = (size_t)(m0 + m) * Nc + n;
                    *reinterpret_cast<float4*>(&C32[o])     = make_float4(v[0], v[1], v[2], v[3]);
                    *reinterpret_cast<float4*>(&C32[o + 4]) = make_float4(v[4], v[5], v[6], v[7]);
                    __half2 h0 = __floats2half2_rn(v[0], v[1]);
                    __half2 h1 = __floats2half2_rn(v[2], v[3]);
                    __half2 h2 = __floats2half2_rn(v[4], v[5]);
                    __half2 h3 = __floats2half2_rn(v[6], v[7]);
                    uint4 op;
                    op.x = *reinterpret_cast<uint32_t*>(&h0);
                    op.y = *reinterpret_cast<uint32_t*>(&h1);
                    op.z = *reinterpret_cast<uint32_t*>(&h2);
                    op.w = *reinterpret_cast<uint32_t*>(&h3);
                    *reinterpret_cast<uint4*>(&C16[o]) = op;
                }
            }
        }
    }
}

// ------------------------- conversion kernels ---------------------------------
__global__ void conv_half_kernel(const float* __restrict__ X, __half* __restrict__ Xh) {
    int i = (blockIdx.x * blockDim.x + threadIdx.x) * 4;
    float4 v = *reinterpret_cast<const float4*>(&X[i]);
    *reinterpret_cast<__half2*>(&Xh[i])     = __floats2half2_rn(v.x, v.y);
    *reinterpret_cast<__half2*>(&Xh[i + 2]) = __floats2half2_rn(v.z, v.w);
}

#define WL0 (DIN * DD)
#define WL1 (DD * DD)
#define WL2 (DD * DD)
#define WL3 (DD * DD)
#define WL4 (DD * DD)
#define WL5 (DD * DH)
#define WTOT (WL0 + WL1 + WL2 + WL3 + WL4 + WL5)

__global__ void conv_weights_kernel(const float* __restrict__ fc1_w, __half* __restrict__ fc1_o,
                                    const float* __restrict__ wh_w,
                                    const float* __restrict__ wt_w, __half* __restrict__ whwt_o,
                                    const float* __restrict__ lin1_w, __half* __restrict__ lin1_o,
                                    const float* __restrict__ lin2_w, __half* __restrict__ lin2_o,
                                    const float* __restrict__ att1_w, __half* __restrict__ att1_o) {
    int i = (blockIdx.x * blockDim.x + threadIdx.x) * 4;
    const float* src; __half* dst; int soff = i, doff;
    if (i < WL0) { src = fc1_w; dst = fc1_o; doff = soff; }
    else if ((soff = i - WL0) < WL1) {
        src = wh_w; dst = whwt_o;
        int k = soff >> 9, n = soff & 511;
        doff = k * DD2 + n;
    }
    else if ((soff = i - WL0 - WL1) < WL2) {
        src = wt_w; dst = whwt_o;
        int k = soff >> 9, n = soff & 511;
        doff = k * DD2 + DD + n;
    }
    else if ((soff = i - WL0 - WL1 - WL2) < WL3) { src = lin1_w; dst = lin1_o; doff = soff; }
    else if ((soff = i - WL0 - WL1 - WL2 - WL3) < WL4) { src = lin2_w; dst = lin2_o; doff = soff; }
    else { soff = i - WL0 - WL1 - WL2 - WL3 - WL4; src = att1_w; dst = att1_o; doff = soff; }
    float4 v = *reinterpret_cast<const float4*>(&src[soff]);
    *reinterpret_cast<__half2*>(&dst[doff])     = __floats2half2_rn(v.x, v.y);
    *reinterpret_cast<__half2*>(&dst[doff + 2]) = __floats2half2_rn(v.z, v.w);
}

__global__ void concat_bias_kernel(const float* __restrict__ b0, const float* __restrict__ b1,
                                   float* __restrict__ out) {
    int i = threadIdx.x + blockIdx.x * blockDim.x;
    out[i] = (i < DD) ? b0[i] : b1[i - DD];
}

// ------------------------- column sums ----------------------------------------
__global__ void colsum_partial_h(const __half* __restrict__ X, float* __restrict__ part) {
    int d = threadIdx.x;
    int r0 = blockIdx.x * ROWS_PER_CHUNK;
    float s = 0.0f;
    #pragma unroll 8
    for (int r = 0; r < ROWS_PER_CHUNK; r++)
        s += __half2float(X[(size_t)(r0 + r) * DD + d]);
    part[blockIdx.x * DD + d] = s;
}

__global__ void colsum_partial(const float* __restrict__ X,
                               const float* __restrict__ w,
                               float* __restrict__ part) {
    int d = threadIdx.x;
    int r0 = blockIdx.x * ROWS_PER_CHUNK;
    float s = 0.0f;
    #pragma unroll 8
    for (int r = 0; r < ROWS_PER_CHUNK; r++)
        s += X[(size_t)(r0 + r) * DD + d] * w[r0 + r];
    part[blockIdx.x * DD + d] = s;
}

__global__ void colmean_finish(const float* __restrict__ part, float* __restrict__ mean) {
    int d = threadIdx.x;
    float s = 0.0f;
    #pragma unroll 8
    for (int c = 0; c < NCHUNK; c++) s += part[c * DD + d];
    mean[d] = s / (float)NROWS;
}

__global__ void mean_update(__half* __restrict__ h16, const float* __restrict__ mean) {
    int i = (blockIdx.x * blockDim.x + threadIdx.x) * 8;
    uint4 pkt = *reinterpret_cast<const uint4*>(&h16[i]);
    __half* hp = reinterpret_cast<__half*>(&pkt);
    int d = i & (DD - 1);
    #pragma unroll
    for (int q = 0; q < 8; q++)
        hp[q] = __float2half((__half2float(hp[q]) + mean[d + q]) * 0.5f);
    *reinterpret_cast<uint4*>(&h16[i]) = pkt;
}

// ------------------------- per-row neighbor aggregation (combined eh|et) -----
__global__ __launch_bounds__(256)
void aggregate_kernel(const __half* __restrict__ ehet, const float* __restrict__ tw,
                      const int* __restrict__ ti,
                      __half* __restrict__ s1h, __half* __restrict__ b1h) {
    const unsigned FULL = 0xFFFFFFFFu;
    __shared__ float red[8 * TK];
    __shared__ float sh_ka[TK];
    int row = blockIdx.x;
    int t = threadIdx.x;
    int wid = t >> 5, lane = t & 31;

    float p[TK];
    {
        float mx = -FLT_MAX;
        #pragma unroll
        for (int k = 0; k < TK; k++) { p[k] = tw[row * TK + k]; mx = fmaxf(mx, p[k]); }
        float s = 0.0f;
        #pragma unroll
        for (int k = 0; k < TK; k++) { p[k] = expf(p[k] - mx); s += p[k]; }
        #pragma unroll
        for (int k = 0; k < TK; k++) p[k] /= s;
    }

    float eh0 = __half2float(ehet[(size_t)row * DD2 + t]);
    float eh1 = __half2float(ehet[(size_t)row * DD2 + t + 256]);
    float Nb[TK][2];
    float partial[TK];

    #pragma unroll
    for (int k = 0; k < TK; k++) {
        int j = ti[row * TK + k];
        Nb[k][0] = __half2float(ehet[(size_t)j * DD2 + DD + t]);
        Nb[k][1] = __half2float(ehet[(size_t)j * DD2 + DD + t + 256]);
        float g0 = tanhf(fmaf(2.0f - p[k], eh0, p[k] * Nb[k][0]));
        float g1 = tanhf(fmaf(2.0f - p[k], eh1, p[k] * Nb[k][1]));
        partial[k] = Nb[k][0] * g0 + Nb[k][1] * g1;
    }

    #pragma unroll
    for (int k = 0; k < TK; k++) {
        #pragma unroll
        for (int off = 16; off > 0; off >>= 1)
            partial[k] += __shfl_down_sync(FULL, partial[k], off);
    }
    if (lane == 0) {
        #pragma unroll
        for (int k = 0; k < TK; k++) red[wid * TK + k] = partial[k];
    }
    __syncthreads();
    if (t < TK) {
        float s = 0.0f;
        #pragma unroll
        for (int w = 0; w < 8; w++) s += red[w * TK + t];
        sh_ka[t] = s;
    }
    __syncthreads();

    float kp[TK];
    {
        float mx = -FLT_MAX;
        #pragma unroll
        for (int k = 0; k < TK; k++) { kp[k] = sh_ka[k]; mx = fmaxf(mx, kp[k]); }
        float s = 0.0f;
        #pragma unroll
        for (int k = 0; k < TK; k++) { kp[k] = expf(kp[k] - mx); s += kp[k]; }
        #pragma unroll
        for (int k = 0; k < TK; k++) kp[k] /= s;
    }

    float en0 = 0.0f, en1 = 0.0f;
    #pragma unroll
    for (int k = 0; k < TK; k++) { en0 = fmaf(kp[k], Nb[k][0], en0); en1 = fmaf(kp[k], Nb[k][1], en1); }

    s1h[(size_t)row * DD + t]       = __float2half(eh0 + en0);
    s1h[(size_t)row * DD + t + 256] = __float2half(eh1 + en1);
    b1h[(size_t)row * DD + t]       = __float2half(eh0 * en0);
    b1h[(size_t)row * DD + t + 256] = __float2half(eh1 * en1);
}

// ------------------------- attention readout ---------------------------------
__global__ void att_mv_kernel(const float* __restrict__ hatt,
                              const float* __restrict__ w2, const float* __restrict__ b2,
                              float* __restrict__ att) {
    const unsigned FULL = 0xFFFFFFFFu;
    int warp = threadIdx.x >> 5;
    int lane = threadIdx.x & 31;
    int row = blockIdx.x * 8 + warp;
    float s = 0.0f;
    for (int d = lane; d < DH; d += 32)
        s = fmaf(hatt[(size_t)row * DH + d], w2[d], s);
    #pragma unroll
    for (int off = 16; off > 0; off >>= 1) s += __shfl_down_sync(FULL, s, off);
    if (lane == 0) att[row] = s + b2[0];
}

__global__ void softmax_n_kernel(const float* __restrict__ att, float* __restrict__ a) {
    __shared__ float red[1024];
    __shared__ float s_max, s_sum;
    int t = threadIdx.x;
    float lm = -FLT_MAX;
    for (int i = t; i < NROWS; i += 1024) lm = fmaxf(lm, att[i]);
    red[t] = lm; __syncthreads();
    for (int s = 512; s > 0; s >>= 1) { if (t < s) red[t] = fmaxf(red[t], red[t + s]); __syncthreads(); }
    if (t == 0) s_max = red[0];
    __syncthreads();
    float ls = 0.0f;
    for (int i = t; i < NROWS; i += 1024) ls += expf(att[i] - s_max);
    red[t] = ls; __syncthreads();
    for (int s = 512; s > 0; s >>= 1) { if (t < s) red[t] += red[t + s]; __syncthreads(); }
    if (t == 0) s_sum = red[0];
    __syncthreads();
    float inv = 1.0f / s_sum;
    for (int i = t; i < NROWS; i += 1024) a[i] = expf(att[i] - s_max) * inv;
}

// ------------------------- final: LN + fc + softmax + argmax -----------------
__global__ void final_kernel(const float* __restrict__ part,
                             const float* __restrict__ ln_g, const float* __restrict__ ln_b,
                             const float* __restrict__ fc_w, const float* __restrict__ fc_b,
                             float* __restrict__ out, int out_size) {
    __shared__ float red[DD];
    int d = threadIdx.x;
    float pooled = 0.0f;
    #pragma unroll 8
    for (int c = 0; c < NCHUNK; c++) pooled += part[c * DD + d];

    red[d] = pooled; __syncthreads();
    for (int s = 256; s > 0; s >>= 1) { if (d < s) red[d] += red[d + s]; __syncthreads(); }
    float mu = red[0] / (float)DD;
    __syncthreads();

    float cen = pooled - mu;
    red[d] = cen * cen; __syncthreads();
    for (int s = 256; s > 0; s >>= 1) { if (d < s) red[d] += red[d + s]; __syncthreads(); }
    float var = red[0] / (float)DD;
    __syncthreads();

    float ln = cen * rsqrtf(var + LN_EPS) * ln_g[d] + ln_b[d];

    red[d] = ln * fc_w[2 * d + 0]; __syncthreads();
    for (int s = 256; s > 0; s >>= 1) { if (d < s) red[d] += red[d + s]; __syncthreads(); }
    float o0 = red[0] + fc_b[0];
    __syncthreads();

    red[d] = ln * fc_w[2 * d + 1]; __syncthreads();
    for (int s = 256; s > 0; s >>= 1) { if (d < s) red[d] += red[d + s]; __syncthreads(); }
    float o1 = red[0] + fc_b[1];

    if (d == 0) {
        float m = fmaxf(o0, o1);
        float e0 = expf(o0 - m), e1 = expf(o1 - m);
        float inv = 1.0f / (e0 + e1);
        if (out_size > 0) out[0] = o0;
        if (out_size > 1) out[1] = o1;
        if (out_size > 2) out[2] = e0 * inv;
        if (out_size > 3) out[3] = e1 * inv;
        if (out_size > 4) out[4] = (o1 > o0) ? 1.0f : 0.0f;
    }
}

// ------------------------- host orchestration --------------------------------
static void* symv(const void* s) {
    void* p = nullptr;
    cudaGetSymbolAddress(&p, s);
    return p;
}

template <int EPI, bool NT, bool ACC, bool TOPK>
static void launch_gemm16(const __half* A, const __half* B, const float* bias,
                          float* C32, __half* C16, int M, int Nc, int K,
                          int lda, int ldb, float alpha,
                          float* cv = nullptr, int* ci = nullptr) {
    static bool attr_done = false;
    if (!attr_done) {
        cudaFuncSetAttribute(gemm16_kernel<EPI, NT, ACC, TOPK>,
                             cudaFuncAttributeMaxDynamicSharedMemorySize, SMEM_BYTES);
        attr_done = true;
    }
    gemm16_kernel<EPI, NT, ACC, TOPK><<<dim3(Nc / 128, M / 128), 256, SMEM_BYTES>>>(
        A, B, bias, C32, C16, M, Nc, K, lda, ldb, alpha, cv, ci);
}

extern "C" void kernel_launch(void* const* d_in, const int* in_sizes, int n_in,
                              void* d_out, int out_size) {
    const float* x      = (const float*)d_in[0];
    const float* fc1_w  = (const float*)d_in[1];
    const float* fc1_b  = (const float*)d_in[2];
    const float* wh_w   = (const float*)d_in[3];
    const float* wh_b   = (const float*)d_in[4];
    const float* wt_w   = (const float*)d_in[5];
    const float* wt_b   = (const float*)d_in[6];
    const float* lin1_w = (const float*)d_in[7];
    const float* lin1_b = (const float*)d_in[8];
    const float* lin2_w = (const float*)d_in[9];
    const float* lin2_b = (const float*)d_in[10];
    const float* att1_w = (const float*)d_in[11];
    const float* att1_b = (const float*)d_in[12];
    const float* att2_w = (const float*)d_in[13];
    const float* att2_b = (const float*)d_in[14];
    const float* ln_g   = (const float*)d_in[15];
    const float* ln_b   = (const float*)d_in[16];
    const float* fc_w   = (const float*)d_in[17];
    const float* fc_b   = (const float*)d_in[18];

    float*  cv      = (float*)symv(g_cand_v);
    int*    ci      = (int*)symv(g_cand_i);
    float*  tw      = (float*)symv(g_tw);
    int*    ti      = (int*)symv(g_ti);
    float*  emb     = (float*)symv(g_emb);
    float*  hatt    = (float*)symv(g_hatt);
    float*  att     = (float*)symv(g_att);
    float*  a       = (float*)symv(g_a);
    float*  part    = (float*)symv(g_part);
    float*  cmean   = (float*)symv(g_colmean);
    __half* xh      = (__half*)symv(g_xh);
    __half* h16     = (__half*)symv(g_h16);
    __half* ehet16  = (__half*)symv(g_ehet16);
    __half* s1h     = (__half*)symv(g_s1h);
    __half* b1h     = (__half*)symv(g_b1h);
    __half* emb16   = (__half*)symv(g_emb16);
    __half* fc1_wh  = (__half*)symv(g_fc1_wh);
    __half* whwt    = (__half*)symv(g_whwt);
    __half* lin1_wh = (__half*)symv(g_lin1_wh);
    __half* lin2_wh = (__half*)symv(g_lin2_wh);
    __half* att1_wh = (__half*)symv(g_att1_wh);
    float*  bias2   = (float*)symv(g_bias2);

    // 0) fp16 conversions + packed wh|wt weight + concat bias
    conv_half_kernel<<<(NROWS * DIN) / 1024, 256>>>(x, xh);
    conv_weights_kernel<<<WTOT / 1024, 256>>>(fc1_w, fc1_wh, wh_w, wt_w, whwt,
                                              lin1_w, lin1_wh, lin2_w, lin2_wh,
                                              att1_w, att1_wh);
    concat_bias_kernel<<<4, 256>>>(wh_b, wt_b, bias2);

    // 1) h16 = half(relu(x @ fc1_w + fc1_b))
    launch_gemm16<1, false, false, false>(xh, fc1_wh, fc1_b, nullptr, h16,
                                          NROWS, DD, DIN, DIN, DD, 1.0f);

    // 2) h16 = half((h16 + colmean(h16)) * 0.5)
    colsum_partial_h<<<NCHUNK, DD>>>(h16, part);
    colmean_finish<<<1, DD>>>(part, cmean);
    mean_update<<<(NROWS * DD) / 2048, 256>>>(h16, cmean);

    // 3) combined [e_h | e_t] = h @ [wh | wt] + [wh_b | wt_b]
    launch_gemm16<0, false, false, false>(h16, whwt, bias2, nullptr, ehet16,
                                          NROWS, DD2, DD, DD, DD2, 1.0f);

    // 4+5) logits GEMM fused with per-tile top-6; candidates -> reduce
    launch_gemm16<0, true, false, true>(ehet16, ehet16 + DD, nullptr, nullptr, nullptr,
                                        NROWS, NROWS, DD, DD2, DD2, SCALE_LOGITS, cv, ci);
    topk_reduce_kernel<<<NROWS / 8, 256>>>(cv, ci, tw, ti);

    // 6) neighbor aggregation -> s1h, b1h
    aggregate_kernel<<<NROWS, 256>>>(ehet16, tw, ti, s1h, b1h);

    // 7) emb = leaky(s1@lin1+b) + leaky(b1@lin2+b)  (fused dual GEMM)
    {
        static bool dual_attr = false;
        if (!dual_attr) {
            cudaFuncSetAttribute(gemm_dual_kernel,
                                 cudaFuncAttributeMaxDynamicSharedMemorySize, DUAL_SMEM);
            dual_attr = true;
        }
        gemm_dual_kernel<<<dim3(DD / 128, NROWS / 128), 256, DUAL_SMEM>>>(
            s1h, lin1_wh, lin1_b, b1h, lin2_wh, lin2_b, emb, emb16, NROWS, DD, DD);
    }

    // 8) attention readout
    launch_gemm16<2, false, false, false>(emb16, att1_wh, att1_b, hatt, nullptr,
                                          NROWS, DH, DD, DD, DH, 1.0f);
    att_mv_kernel<<<NROWS / 8, 256>>>(hatt, att2_w, att2_b, att);
    softmax_n_kernel<<<1, 1024>>>(att, a);

    // 9) pooled = sum_i a_i * emb_i
    colsum_partial<<<NCHUNK, DD>>>(emb, a, part);

    // 10) LN + fc + softmax + argmax
    final_kernel<<<1, DD>>>(part, ln_g, ln_b, fc_w, fc_b, (float*)d_out, out_size);
}

// round 17
// speedup vs baseline: 1.1646x; 1.1646x over previous
#include <cuda_runtime.h>
#include <cuda_fp16.h>
#include <mma.h>
#include <math.h>
#include <float.h>
#include <stdint.h>
#include <type_traits>

using namespace nvcuda;

#define NROWS 8192
#define DIN   1024
#define DD    512
#define DD2   1024     // combined eh|et width
#define DH    256      // D/2
#define TK    6
#define NCHUNK 128
#define ROWS_PER_CHUNK (NROWS / NCHUNK)
#define LN_EPS 1e-5f
#define SCALE_LOGITS 0.044194173824159216f  // 512^-0.5

// ------------------------- scratch (device globals; no cudaMalloc allowed) ---
__device__ __half g_logits16[(size_t)NROWS * NROWS];  // 128 MB
__device__ float  g_tw[NROWS * TK];
__device__ int    g_ti[NROWS * TK];
__device__ float  g_emb[NROWS * DD];
__device__ __half g_hatt16[NROWS * DH];
__device__ float  g_att[NROWS];
__device__ float  g_a[NROWS];
__device__ float  g_part[NCHUNK * DD];
__device__ float  g_colmean[DD];
// fp16 operand buffers
__device__ __half g_xh[NROWS * DIN];
__device__ __half g_h16[NROWS * DD];
__device__ __half g_ehet16[NROWS * DD2];   // eh | et combined, 16 MB
__device__ __half g_s1h[NROWS * DD];
__device__ __half g_b1h[NROWS * DD];
__device__ __half g_emb16[NROWS * DD];
// fp16 weights
__device__ __half g_fc1_wh[DIN * DD];
__device__ __half g_whwt[DD * DD2];        // wh | wt packed [512, 1024]
__device__ __half g_lin1_wh[DD * DD];
__device__ __half g_lin2_wh[DD * DD];
__device__ __half g_att1_wh[DD * DH];
__device__ float  g_bias2[DD2];            // wh_b | wt_b

// ------------------------- cp.async helpers ----------------------------------
__device__ __forceinline__ void cp_async16(void* smem_ptr, const void* gptr) {
    unsigned saddr = (unsigned)__cvta_generic_to_shared(smem_ptr);
    asm volatile("cp.async.cg.shared.global [%0], [%1], 16;\n" :: "r"(saddr), "l"(gptr));
}
__device__ __forceinline__ void cp_commit() { asm volatile("cp.async.commit_group;\n"); }
__device__ __forceinline__ void cp_wait0()  { asm volatile("cp.async.wait_group 0;\n"); }

// ------------------------- fp16 wmma GEMM: BK=64, 2-stage, occ-2 --------------
#define LDA   72      // halves: 64 + 8 pad
#define LDBN  136     // halves: 128 + 8 pad
#define LDC   68      // floats
#define LDP   136     // halves (dual-kernel stash)
#define A_H   (128 * LDA)                    // 9216 halves
#define B_H   9216
#define STAGE_H (A_H + B_H)                   // 18432 halves = 36864 B
#define SMEM_BYTES (2 * STAGE_H * 2)          // 73728 B -> 2 CTAs/SM
#define DUAL_SMEM (SMEM_BYTES + 128 * LDP * 2)  // 108544 B

template <bool NT>
__device__ __forceinline__ void load_tiles(__half* As, __half* Bs,
                                           const __half* __restrict__ A,
                                           const __half* __restrict__ B,
                                           int m0, int n0, int k0,
                                           int lda, int ldb, int tid) {
    #pragma unroll
    for (int f = tid; f < 1024; f += 256) {
        int m = f >> 3, kq = (f & 7) << 3;
        cp_async16(&As[m * LDA + kq], &A[(size_t)(m0 + m) * lda + k0 + kq]);
    }
    if (NT) {
        #pragma unroll
        for (int f = tid; f < 1024; f += 256) {
            int n = f >> 3, kq = (f & 7) << 3;
            cp_async16(&Bs[n * LDA + kq], &B[(size_t)(n0 + n) * ldb + k0 + kq]);
        }
    } else {
        #pragma unroll
        for (int f = tid; f < 1024; f += 256) {
            int k = f >> 4, nq = (f & 15) << 3;
            cp_async16(&Bs[k * LDBN + nq], &B[(size_t)(k0 + k) * ldb + n0 + nq]);
        }
    }
}

template <bool NT>
__device__ __forceinline__ void gemm_mainloop(
        __half* smem, const __half* __restrict__ A, const __half* __restrict__ B,
        wmma::fragment<wmma::accumulator, 16, 16, 16, float> (&acc)[2][4],
        int m0, int n0, int K, int lda, int ldb, int tid, int m_off, int n_off) {
    using BLayout = typename std::conditional<NT, wmma::col_major, wmma::row_major>::type;
    const int NC = K / 64;
    load_tiles<NT>(smem, smem + A_H, A, B, m0, n0, 0, lda, ldb, tid);
    cp_commit();
    for (int i = 0; i < NC; i++) {
        cp_wait0();
        __syncthreads();
        __half* As = smem + (i & 1) * STAGE_H;
        __half* Bs = As + A_H;
        if (i + 1 < NC) {
            __half* An = smem + ((i + 1) & 1) * STAGE_H;
            load_tiles<NT>(An, An + A_H, A, B, m0, n0, (i + 1) * 64, lda, ldb, tid);
            cp_commit();
        }
        #pragma unroll
        for (int kk = 0; kk < 4; kk++) {
            wmma::fragment<wmma::matrix_a, 16, 16, 16, __half, wmma::row_major> af[2];
            wmma::fragment<wmma::matrix_b, 16, 16, 16, __half, BLayout> bf[4];
            #pragma unroll
            for (int i2 = 0; i2 < 2; i2++)
                wmma::load_matrix_sync(af[i2], &As[(m_off + i2 * 16) * LDA + kk * 16], LDA);
            #pragma unroll
            for (int j = 0; j < 4; j++) {
                if (NT)
                    wmma::load_matrix_sync(bf[j], &Bs[(n_off + j * 16) * LDA + kk * 16], LDA);
                else
                    wmma::load_matrix_sync(bf[j], &Bs[kk * 16 * LDBN + n_off + j * 16], LDBN);
            }
            #pragma unroll
            for (int i2 = 0; i2 < 2; i2++)
                #pragma unroll
                for (int j = 0; j < 4; j++)
                    wmma::mma_sync(acc[i2][j], af[i2], bf[j], acc[i2][j]);
        }
    }
}

template <int EPI, bool NT, bool ACC>
__global__ __launch_bounds__(256, 2)
void gemm16_kernel(const __half* __restrict__ A, const __half* __restrict__ B,
                   const float* __restrict__ bias, float* __restrict__ C32,
                   __half* __restrict__ C16, int M, int Nc, int K,
                   int lda, int ldb, float alpha) {
    extern __shared__ __half smem[];
    const int tid    = threadIdx.x;
    const int warpId = tid >> 5;
    const int m_off  = (warpId >> 1) * 32;
    const int n_off  = (warpId & 1) * 64;
    const int warp_n = warpId & 1;
    const int m0 = blockIdx.y * 128;
    const int n0 = blockIdx.x * 128;

    wmma::fragment<wmma::accumulator, 16, 16, 16, float> acc[2][4];
    #pragma unroll
    for (int i = 0; i < 2; i++)
        #pragma unroll
        for (int j = 0; j < 4; j++)
            wmma::fill_fragment(acc[i][j], 0.0f);

    gemm_mainloop<NT>(smem, A, B, acc, m0, n0, K, lda, ldb, tid, m_off, n_off);

    // vectorized epilogue: 8 consecutive columns per thread
    float* Cs = (float*)smem;
    #pragma unroll
    for (int h = 0; h < 2; h++) {
        __syncthreads();
        if (warp_n == h) {
            #pragma unroll
            for (int i = 0; i < 2; i++)
                #pragma unroll
                for (int j = 0; j < 4; j++)
                    wmma::store_matrix_sync(&Cs[(m_off + i * 16) * LDC + j * 16],
                                            acc[i][j], LDC, wmma::mem_row_major);
        }
        __syncthreads();
        #pragma unroll
        for (int e = tid; e < 1024; e += 256) {
            int m = e >> 3, c8 = (e & 7) << 3;
            int n = n0 + h * 64 + c8;
            float4 v0 = *reinterpret_cast<const float4*>(&Cs[m * LDC + c8]);
            float4 v1 = *reinterpret_cast<const float4*>(&Cs[m * LDC + c8 + 4]);
            float v[8] = {v0.x, v0.y, v0.z, v0.w, v1.x, v1.y, v1.z, v1.w};
            size_t o = (size_t)(m0 + m) * Nc + n;
            float acc32[8];
            if (ACC) {
                float4 a0 = *reinterpret_cast<const float4*>(&C32[o]);
                float4 a1 = *reinterpret_cast<const float4*>(&C32[o + 4]);
                acc32[0] = a0.x; acc32[1] = a0.y; acc32[2] = a0.z; acc32[3] = a0.w;
                acc32[4] = a1.x; acc32[5] = a1.y; acc32[6] = a1.z; acc32[7] = a1.w;
            }
            #pragma unroll
            for (int q = 0; q < 8; q++) {
                float t = v[q] * alpha;
                if (bias) t += bias[n + q];
                if (EPI == 1) t = fmaxf(t, 0.0f);
                else if (EPI == 2) t = (t > 0.0f) ? t : 0.01f * t;
                if (ACC) t += acc32[q];
                v[q] = t;
            }
            if (C32) {
                *reinterpret_cast<float4*>(&C32[o])     = make_float4(v[0], v[1], v[2], v[3]);
                *reinterpret_cast<float4*>(&C32[o + 4]) = make_float4(v[4], v[5], v[6], v[7]);
            }
            if (C16) {
                __half2 h0 = __floats2half2_rn(v[0], v[1]);
                __half2 h1 = __floats2half2_rn(v[2], v[3]);
                __half2 h2 = __floats2half2_rn(v[4], v[5]);
                __half2 h3 = __floats2half2_rn(v[6], v[7]);
                uint4 pkt;
                pkt.x = *reinterpret_cast<uint32_t*>(&h0);
                pkt.y = *reinterpret_cast<uint32_t*>(&h1);
                pkt.z = *reinterpret_cast<uint32_t*>(&h2);
                pkt.w = *reinterpret_cast<uint32_t*>(&h3);
                *reinterpret_cast<uint4*>(&C16[o]) = pkt;
            }
        }
    }
}

// ---------- fused dual GEMM: emb = leaky(A1@B1+b1) + leaky(A2@B2+b2) ----------
__global__ __launch_bounds__(256, 2)
void gemm_dual_kernel(const __half* __restrict__ A1, const __half* __restrict__ B1,
                      const float* __restrict__ bias1,
                      const __half* __restrict__ A2, const __half* __restrict__ B2,
                      const float* __restrict__ bias2,
                      float* __restrict__ C32, __half* __restrict__ C16,
                      int M, int Nc, int K) {
    extern __shared__ __half smem[];
    __half* P = smem + 2 * STAGE_H;
    const int tid    = threadIdx.x;
    const int warpId = tid >> 5;
    const int m_off  = (warpId >> 1) * 32;
    const int n_off  = (warpId & 1) * 64;
    const int warp_n = warpId & 1;
    const int m0 = blockIdx.y * 128;
    const int n0 = blockIdx.x * 128;

    float* Cs = (float*)smem;

    #pragma unroll
    for (int pass = 0; pass < 2; pass++) {
        const __half* A = pass ? A2 : A1;
        const __half* B = pass ? B2 : B1;
        const float* bias = pass ? bias2 : bias1;

        wmma::fragment<wmma::accumulator, 16, 16, 16, float> acc[2][4];
        #pragma unroll
        for (int i = 0; i < 2; i++)
            #pragma unroll
            for (int j = 0; j < 4; j++)
                wmma::fill_fragment(acc[i][j], 0.0f);

        __syncthreads();
        gemm_mainloop<false>(smem, A, B, acc, m0, n0, K, Nc, Nc, tid, m_off, n_off);

        #pragma unroll
        for (int h = 0; h < 2; h++) {
            __syncthreads();
            if (warp_n == h) {
                #pragma unroll
                for (int i = 0; i < 2; i++)
                    #pragma unroll
                    for (int j = 0; j < 4; j++)
                        wmma::store_matrix_sync(&Cs[(m_off + i * 16) * LDC + j * 16],
                                                acc[i][j], LDC, wmma::mem_row_major);
            }
            __syncthreads();
            #pragma unroll
            for (int e = tid; e < 1024; e += 256) {
                int m = e >> 3, c8 = (e & 7) << 3;
                int n = n0 + h * 64 + c8;
                int pc = h * 64 + c8;
                float4 v0 = *reinterpret_cast<const float4*>(&Cs[m * LDC + c8]);
                float4 v1 = *reinterpret_cast<const float4*>(&Cs[m * LDC + c8 + 4]);
                float v[8] = {v0.x, v0.y, v0.z, v0.w, v1.x, v1.y, v1.z, v1.w};
                #pragma unroll
                for (int q = 0; q < 8; q++) {
                    float t = v[q] + bias[n + q];
                    v[q] = (t > 0.0f) ? t : 0.01f * t;
                }
                if (pass == 0) {
                    __half2 h0 = __floats2half2_rn(v[0], v[1]);
                    __half2 h1 = __floats2half2_rn(v[2], v[3]);
                    __half2 h2 = __floats2half2_rn(v[4], v[5]);
                    __half2 h3 = __floats2half2_rn(v[6], v[7]);
                    uint4 pkt;
                    pkt.x = *reinterpret_cast<uint32_t*>(&h0);
                    pkt.y = *reinterpret_cast<uint32_t*>(&h1);
                    pkt.z = *reinterpret_cast<uint32_t*>(&h2);
                    pkt.w = *reinterpret_cast<uint32_t*>(&h3);
                    *reinterpret_cast<uint4*>(&P[m * LDP + pc]) = pkt;
                } else {
                    uint4 pkt = *reinterpret_cast<const uint4*>(&P[m * LDP + pc]);
                    const __half* hp = reinterpret_cast<const __half*>(&pkt);
                    #pragma unroll
                    for (int q = 0; q < 8; q++) v[q] += __half2float(hp[q]);
                    size_t o = (size_t)(m0 + m) * Nc + n;
                    *reinterpret_cast<float4*>(&C32[o])     = make_float4(v[0], v[1], v[2], v[3]);
                    *reinterpret_cast<float4*>(&C32[o + 4]) = make_float4(v[4], v[5], v[6], v[7]);
                    __half2 h0 = __floats2half2_rn(v[0], v[1]);
                    __half2 h1 = __floats2half2_rn(v[2], v[3]);
                    __half2 h2 = __floats2half2_rn(v[4], v[5]);
                    __half2 h3 = __floats2half2_rn(v[6], v[7]);
                    uint4 op;
                    op.x = *reinterpret_cast<uint32_t*>(&h0);
                    op.y = *reinterpret_cast<uint32_t*>(&h1);
                    op.z = *reinterpret_cast<uint32_t*>(&h2);
                    op.w = *reinterpret_cast<uint32_t*>(&h3);
                    *reinterpret_cast<uint4*>(&C16[o]) = op;
                }
            }
        }
    }
}

// ------------------------- conversion kernels ---------------------------------
__global__ void conv_half_kernel(const float* __restrict__ X, __half* __restrict__ Xh) {
    int i = (blockIdx.x * blockDim.x + threadIdx.x) * 4;
    float4 v = *reinterpret_cast<const float4*>(&X[i]);
    *reinterpret_cast<__half2*>(&Xh[i])     = __floats2half2_rn(v.x, v.y);
    *reinterpret_cast<__half2*>(&Xh[i + 2]) = __floats2half2_rn(v.z, v.w);
}

#define WL0 (DIN * DD)
#define WL1 (DD * DD)
#define WL2 (DD * DD)
#define WL3 (DD * DD)
#define WL4 (DD * DD)
#define WL5 (DD * DH)
#define WTOT (WL0 + WL1 + WL2 + WL3 + WL4 + WL5)

__global__ void conv_weights_kernel(const float* __restrict__ fc1_w, __half* __restrict__ fc1_o,
                                    const float* __restrict__ wh_w,
                                    const float* __restrict__ wt_w, __half* __restrict__ whwt_o,
                                    const float* __restrict__ lin1_w, __half* __restrict__ lin1_o,
                                    const float* __restrict__ lin2_w, __half* __restrict__ lin2_o,
                                    const float* __restrict__ att1_w, __half* __restrict__ att1_o) {
    int i = (blockIdx.x * blockDim.x + threadIdx.x) * 4;
    const float* src; __half* dst; int soff = i, doff;
    if (i < WL0) { src = fc1_w; dst = fc1_o; doff = soff; }
    else if ((soff = i - WL0) < WL1) {
        src = wh_w; dst = whwt_o;
        int k = soff >> 9, n = soff & 511;
        doff = k * DD2 + n;
    }
    else if ((soff = i - WL0 - WL1) < WL2) {
        src = wt_w; dst = whwt_o;
        int k = soff >> 9, n = soff & 511;
        doff = k * DD2 + DD + n;
    }
    else if ((soff = i - WL0 - WL1 - WL2) < WL3) { src = lin1_w; dst = lin1_o; doff = soff; }
    else if ((soff = i - WL0 - WL1 - WL2 - WL3) < WL4) { src = lin2_w; dst = lin2_o; doff = soff; }
    else { soff = i - WL0 - WL1 - WL2 - WL3 - WL4; src = att1_w; dst = att1_o; doff = soff; }
    float4 v = *reinterpret_cast<const float4*>(&src[soff]);
    *reinterpret_cast<__half2*>(&dst[doff])     = __floats2half2_rn(v.x, v.y);
    *reinterpret_cast<__half2*>(&dst[doff + 2]) = __floats2half2_rn(v.z, v.w);
}

__global__ void concat_bias_kernel(const float* __restrict__ b0, const float* __restrict__ b1,
                                   float* __restrict__ out) {
    int i = threadIdx.x + blockIdx.x * blockDim.x;
    out[i] = (i < DD) ? b0[i] : b1[i - DD];
}

// ------------------------- column sums ----------------------------------------
__global__ void colsum_partial_h(const __half* __restrict__ X, float* __restrict__ part) {
    int d = threadIdx.x;
    int r0 = blockIdx.x * ROWS_PER_CHUNK;
    float s = 0.0f;
    #pragma unroll 8
    for (int r = 0; r < ROWS_PER_CHUNK; r++)
        s += __half2float(X[(size_t)(r0 + r) * DD + d]);
    part[blockIdx.x * DD + d] = s;
}

__global__ void colsum_partial(const float* __restrict__ X,
                               const float* __restrict__ w,
                               float* __restrict__ part) {
    int d = threadIdx.x;
    int r0 = blockIdx.x * ROWS_PER_CHUNK;
    float s = 0.0f;
    #pragma unroll 8
    for (int r = 0; r < ROWS_PER_CHUNK; r++)
        s += X[(size_t)(r0 + r) * DD + d] * w[r0 + r];
    part[blockIdx.x * DD + d] = s;
}

__global__ void colmean_finish(const float* __restrict__ part, float* __restrict__ mean) {
    int d = threadIdx.x;
    float s = 0.0f;
    #pragma unroll 8
    for (int c = 0; c < NCHUNK; c++) s += part[c * DD + d];
    mean[d] = s / (float)NROWS;
}

__global__ void mean_update(__half* __restrict__ h16, const float* __restrict__ mean) {
    int i = (blockIdx.x * blockDim.x + threadIdx.x) * 8;
    uint4 pkt = *reinterpret_cast<const uint4*>(&h16[i]);
    __half* hp = reinterpret_cast<__half*>(&pkt);
    int d = i & (DD - 1);
    #pragma unroll
    for (int q = 0; q < 8; q++)
        hp[q] = __float2half((__half2float(hp[q]) + mean[d + q]) * 0.5f);
    *reinterpret_cast<uint4*>(&h16[i]) = pkt;
}

// ------------------------- top-6 per row (prefetch-pipelined fp16) -----------
__global__ void topk_kernel(const __half* __restrict__ logits,
                            float* __restrict__ tw, int* __restrict__ ti) {
    const unsigned FULL = 0xFFFFFFFFu;
    int warp = threadIdx.x >> 5;
    int lane = threadIdx.x & 31;
    int row = blockIdx.x * 8 + warp;

    const __half* rp = logits + (size_t)row * NROWS;

    float val[TK];
    int   idx[TK];
    #pragma unroll
    for (int k = 0; k < TK; k++) { val[k] = -FLT_MAX; idx[k] = 0x7FFFFFFF; }

    const int NIT = NROWS / 256;
    uint4 pkt = *reinterpret_cast<const uint4*>(rp + lane * 8);
    for (int it = 0; it < NIT; it++) {
        uint4 nxt;
        if (it + 1 < NIT)
            nxt = *reinterpret_cast<const uint4*>(rp + (it + 1) * 256 + lane * 8);
        int jbase = it * 256 + lane * 8;
        const __half* hp = reinterpret_cast<const __half*>(&pkt);
        #pragma unroll
        for (int e = 0; e < 8; e++) {
            float v = __half2float(hp[e]);
            if (v > val[TK - 1]) {
                int j = jbase + e;
                int pos = TK - 1;
                #pragma unroll
                for (int k = TK - 2; k >= 0; k--) {
                    if (v > val[k]) { val[k + 1] = val[k]; idx[k + 1] = idx[k]; pos = k; }
                }
                val[pos] = v; idx[pos] = j;
            }
        }
        pkt = nxt;
    }

    int head = 0;
    for (int r = 0; r < TK; r++) {
        float bv = (head < TK) ? val[head] : -FLT_MAX;
        int   bi = (head < TK) ? idx[head] : 0x7FFFFFFF;
        int   bl = lane;
        #pragma unroll
        for (int off = 16; off > 0; off >>= 1) {
            float ov = __shfl_down_sync(FULL, bv, off);
            int   oi = __shfl_down_sync(FULL, bi, off);
            int   ol = __shfl_down_sync(FULL, bl, off);
            if (ov > bv || (ov == bv && oi < bi)) { bv = ov; bi = oi; bl = ol; }
        }
        bv = __shfl_sync(FULL, bv, 0);
        bi = __shfl_sync(FULL, bi, 0);
        bl = __shfl_sync(FULL, bl, 0);
        if (lane == 0) { tw[row * TK + r] = bv; ti[row * TK + r] = bi; }
        if (lane == bl) head++;
    }
}

// ------------------------- per-row neighbor aggregation (combined eh|et) -----
__global__ __launch_bounds__(256)
void aggregate_kernel(const __half* __restrict__ ehet, const float* __restrict__ tw,
                      const int* __restrict__ ti,
                      __half* __restrict__ s1h, __half* __restrict__ b1h) {
    const unsigned FULL = 0xFFFFFFFFu;
    __shared__ float red[8 * TK];
    __shared__ float sh_ka[TK];
    int row = blockIdx.x;
    int t = threadIdx.x;
    int wid = t >> 5, lane = t & 31;

    float p[TK];
    {
        float mx = -FLT_MAX;
        #pragma unroll
        for (int k = 0; k < TK; k++) { p[k] = tw[row * TK + k]; mx = fmaxf(mx, p[k]); }
        float s = 0.0f;
        #pragma unroll
        for (int k = 0; k < TK; k++) { p[k] = expf(p[k] - mx); s += p[k]; }
        #pragma unroll
        for (int k = 0; k < TK; k++) p[k] /= s;
    }

    float eh0 = __half2float(ehet[(size_t)row * DD2 + t]);
    float eh1 = __half2float(ehet[(size_t)row * DD2 + t + 256]);
    float Nb[TK][2];
    float partial[TK];

    #pragma unroll
    for (int k = 0; k < TK; k++) {
        int j = ti[row * TK + k];
        Nb[k][0] = __half2float(ehet[(size_t)j * DD2 + DD + t]);
        Nb[k][1] = __half2float(ehet[(size_t)j * DD2 + DD + t + 256]);
        float g0 = tanhf(fmaf(2.0f - p[k], eh0, p[k] * Nb[k][0]));
        float g1 = tanhf(fmaf(2.0f - p[k], eh1, p[k] * Nb[k][1]));
        partial[k] = Nb[k][0] * g0 + Nb[k][1] * g1;
    }

    #pragma unroll
    for (int k = 0; k < TK; k++) {
        #pragma unroll
        for (int off = 16; off > 0; off >>= 1)
            partial[k] += __shfl_down_sync(FULL, partial[k], off);
    }
    if (lane == 0) {
        #pragma unroll
        for (int k = 0; k < TK; k++) red[wid * TK + k] = partial[k];
    }
    __syncthreads();
    if (t < TK) {
        float s = 0.0f;
        #pragma unroll
        for (int w = 0; w < 8; w++) s += red[w * TK + t];
        sh_ka[t] = s;
    }
    __syncthreads();

    float kp[TK];
    {
        float mx = -FLT_MAX;
        #pragma unroll
        for (int k = 0; k < TK; k++) { kp[k] = sh_ka[k]; mx = fmaxf(mx, kp[k]); }
        float s = 0.0f;
        #pragma unroll
        for (int k = 0; k < TK; k++) { kp[k] = expf(kp[k] - mx); s += kp[k]; }
        #pragma unroll
        for (int k = 0; k < TK; k++) kp[k] /= s;
    }

    float en0 = 0.0f, en1 = 0.0f;
    #pragma unroll
    for (int k = 0; k < TK; k++) { en0 = fmaf(kp[k], Nb[k][0], en0); en1 = fmaf(kp[k], Nb[k][1], en1); }

    s1h[(size_t)row * DD + t]       = __float2half(eh0 + en0);
    s1h[(size_t)row * DD + t + 256] = __float2half(eh1 + en1);
    b1h[(size_t)row * DD + t]       = __float2half(eh0 * en0);
    b1h[(size_t)row * DD + t + 256] = __float2half(eh1 * en1);
}

// ------------------------- attention readout (fp16 hatt) ----------------------
__global__ void att_mv_kernel(const __half* __restrict__ hatt,
                              const float* __restrict__ w2, const float* __restrict__ b2,
                              float* __restrict__ att) {
    const unsigned FULL = 0xFFFFFFFFu;
    int warp = threadIdx.x >> 5;
    int lane = threadIdx.x & 31;
    int row = blockIdx.x * 8 + warp;
    const __half* rp = hatt + (size_t)row * DH;
    float s = 0.0f;
    // 8 halves per lane: 256 = 32 lanes * 8
    uint4 pkt = *reinterpret_cast<const uint4*>(rp + lane * 8);
    const __half* hp = reinterpret_cast<const __half*>(&pkt);
    #pragma unroll
    for (int e = 0; e < 8; e++)
        s = fmaf(__half2float(hp[e]), w2[lane * 8 + e], s);
    #pragma unroll
    for (int off = 16; off > 0; off >>= 1) s += __shfl_down_sync(FULL, s, off);
    if (lane == 0) att[row] = s + b2[0];
}

__global__ void softmax_n_kernel(const float* __restrict__ att, float* __restrict__ a) {
    __shared__ float red[1024];
    __shared__ float s_max, s_sum;
    int t = threadIdx.x;
    float lm = -FLT_MAX;
    for (int i = t; i < NROWS; i += 1024) lm = fmaxf(lm, att[i]);
    red[t] = lm; __syncthreads();
    for (int s = 512; s > 0; s >>= 1) { if (t < s) red[t] = fmaxf(red[t], red[t + s]); __syncthreads(); }
    if (t == 0) s_max = red[0];
    __syncthreads();
    float ls = 0.0f;
    for (int i = t; i < NROWS; i += 1024) ls += expf(att[i] - s_max);
    red[t] = ls; __syncthreads();
    for (int s = 512; s > 0; s >>= 1) { if (t < s) red[t] += red[t + s]; __syncthreads(); }
    if (t == 0) s_sum = red[0];
    __syncthreads();
    float inv = 1.0f / s_sum;
    for (int i = t; i < NROWS; i += 1024) a[i] = expf(att[i] - s_max) * inv;
}

// ------------------------- final: LN + fc + softmax + argmax -----------------
__global__ void final_kernel(const float* __restrict__ part,
                             const float* __restrict__ ln_g, const float* __restrict__ ln_b,
                             const float* __restrict__ fc_w, const float* __restrict__ fc_b,
                             float* __restrict__ out, int out_size) {
    __shared__ float red[DD];
    int d = threadIdx.x;
    float pooled = 0.0f;
    #pragma unroll 8
    for (int c = 0; c < NCHUNK; c++) pooled += part[c * DD + d];

    red[d] = pooled; __syncthreads();
    for (int s = 256; s > 0; s >>= 1) { if (d < s) red[d] += red[d + s]; __syncthreads(); }
    float mu = red[0] / (float)DD;
    __syncthreads();

    float cen = pooled - mu;
    red[d] = cen * cen; __syncthreads();
    for (int s = 256; s > 0; s >>= 1) { if (d < s) red[d] += red[d + s]; __syncthreads(); }
    float var = red[0] / (float)DD;
    __syncthreads();

    float ln = cen * rsqrtf(var + LN_EPS) * ln_g[d] + ln_b[d];

    red[d] = ln * fc_w[2 * d + 0]; __syncthreads();
    for (int s = 256; s > 0; s >>= 1) { if (d < s) red[d] += red[d + s]; __syncthreads(); }
    float o0 = red[0] + fc_b[0];
    __syncthreads();

    red[d] = ln * fc_w[2 * d + 1]; __syncthreads();
    for (int s = 256; s > 0; s >>= 1) { if (d < s) red[d] += red[d + s]; __syncthreads(); }
    float o1 = red[0] + fc_b[1];

    if (d == 0) {
        float m = fmaxf(o0, o1);
        float e0 = expf(o0 - m), e1 = expf(o1 - m);
        float inv = 1.0f / (e0 + e1);
        if (out_size > 0) out[0] = o0;
        if (out_size > 1) out[1] = o1;
        if (out_size > 2) out[2] = e0 * inv;
        if (out_size > 3) out[3] = e1 * inv;
        if (out_size > 4) out[4] = (o1 > o0) ? 1.0f : 0.0f;
    }
}

// ------------------------- host orchestration --------------------------------
static void* symv(const void* s) {
    void* p = nullptr;
    cudaGetSymbolAddress(&p, s);
    return p;
}

template <int EPI, bool NT, bool ACC>
static void launch_gemm16(const __half* A, const __half* B, const float* bias,
                          float* C32, __half* C16, int M, int Nc, int K,
                          int lda, int ldb, float alpha) {
    static bool attr_done = false;
    if (!attr_done) {
        cudaFuncSetAttribute(gemm16_kernel<EPI, NT, ACC>,
                             cudaFuncAttributeMaxDynamicSharedMemorySize, SMEM_BYTES);
        attr_done = true;
    }
    gemm16_kernel<EPI, NT, ACC><<<dim3(Nc / 128, M / 128), 256, SMEM_BYTES>>>(
        A, B, bias, C32, C16, M, Nc, K, lda, ldb, alpha);
}

extern "C" void kernel_launch(void* const* d_in, const int* in_sizes, int n_in,
                              void* d_out, int out_size) {
    const float* x      = (const float*)d_in[0];
    const float* fc1_w  = (const float*)d_in[1];
    const float* fc1_b  = (const float*)d_in[2];
    const float* wh_w   = (const float*)d_in[3];
    const float* wh_b   = (const float*)d_in[4];
    const float* wt_w   = (const float*)d_in[5];
    const float* wt_b   = (const float*)d_in[6];
    const float* lin1_w = (const float*)d_in[7];
    const float* lin1_b = (const float*)d_in[8];
    const float* lin2_w = (const float*)d_in[9];
    const float* lin2_b = (const float*)d_in[10];
    const float* att1_w = (const float*)d_in[11];
    const float* att1_b = (const float*)d_in[12];
    const float* att2_w = (const float*)d_in[13];
    const float* att2_b = (const float*)d_in[14];
    const float* ln_g   = (const float*)d_in[15];
    const float* ln_b   = (const float*)d_in[16];
    const float* fc_w   = (const float*)d_in[17];
    const float* fc_b   = (const float*)d_in[18];

    __half* logits16= (__half*)symv(g_logits16);
    float*  tw      = (float*)symv(g_tw);
    int*    ti      = (int*)symv(g_ti);
    float*  emb     = (float*)symv(g_emb);
    __half* hatt16  = (__half*)symv(g_hatt16);
    float*  att     = (float*)symv(g_att);
    float*  a       = (float*)symv(g_a);
    float*  part    = (float*)symv(g_part);
    float*  cmean   = (float*)symv(g_colmean);
    __half* xh      = (__half*)symv(g_xh);
    __half* h16     = (__half*)symv(g_h16);
    __half* ehet16  = (__half*)symv(g_ehet16);
    __half* s1h     = (__half*)symv(g_s1h);
    __half* b1h     = (__half*)symv(g_b1h);
    __half* emb16   = (__half*)symv(g_emb16);
    __half* fc1_wh  = (__half*)symv(g_fc1_wh);
    __half* whwt    = (__half*)symv(g_whwt);
    __half* lin1_wh = (__half*)symv(g_lin1_wh);
    __half* lin2_wh = (__half*)symv(g_lin2_wh);
    __half* att1_wh = (__half*)symv(g_att1_wh);
    float*  bias2   = (float*)symv(g_bias2);

    // 0) fp16 conversions + packed wh|wt weight + concat bias
    conv_half_kernel<<<(NROWS * DIN) / 1024, 256>>>(x, xh);
    conv_weights_kernel<<<WTOT / 1024, 256>>>(fc1_w, fc1_wh, wh_w, wt_w, whwt,
                                              lin1_w, lin1_wh, lin2_w, lin2_wh,
                                              att1_w, att1_wh);
    concat_bias_kernel<<<4, 256>>>(wh_b, wt_b, bias2);

    // 1) h16 = half(relu(x @ fc1_w + fc1_b))
    launch_gemm16<1, false, false>(xh, fc1_wh, fc1_b, nullptr, h16,
                                   NROWS, DD, DIN, DIN, DD, 1.0f);

    // 2) h16 = half((h16 + colmean(h16)) * 0.5)
    colsum_partial_h<<<NCHUNK, DD>>>(h16, part);
    colmean_finish<<<1, DD>>>(part, cmean);
    mean_update<<<(NROWS * DD) / 2048, 256>>>(h16, cmean);

    // 3) combined [e_h | e_t] = h @ [wh | wt] + [wh_b | wt_b]
    launch_gemm16<0, false, false>(h16, whwt, bias2, nullptr, ehet16,
                                   NROWS, DD2, DD, DD, DD2, 1.0f);

    // 4) logits = SCALE * e_h @ e_t^T  (NT, strided operands)
    launch_gemm16<0, true, false>(ehet16, ehet16 + DD, nullptr, nullptr, logits16,
                                  NROWS, NROWS, DD, DD2, DD2, SCALE_LOGITS);

    // 5) top-6 per row
    topk_kernel<<<NROWS / 8, 256>>>(logits16, tw, ti);

    // 6) neighbor aggregation -> s1h, b1h
    aggregate_kernel<<<NROWS, 256>>>(ehet16, tw, ti, s1h, b1h);

    // 7) emb = leaky(s1@lin1+b) + leaky(b1@lin2+b)  (fused dual GEMM)
    {
        static bool dual_attr = false;
        if (!dual_attr) {
            cudaFuncSetAttribute(gemm_dual_kernel,
                                 cudaFuncAttributeMaxDynamicSharedMemorySize, DUAL_SMEM);
            dual_attr = true;
        }
        gemm_dual_kernel<<<dim3(DD / 128, NROWS / 128), 256, DUAL_SMEM>>>(
            s1h, lin1_wh, lin1_b, b1h, lin2_wh, lin2_b, emb, emb16, NROWS, DD, DD);
    }

    // 8) attention readout (hatt in fp16)
    launch_gemm16<2, false, false>(emb16, att1_wh, att1_b, nullptr, hatt16,
                                   NROWS, DH, DD, DD, DH, 1.0f);
    att_mv_kernel<<<NROWS / 8, 256>>>(hatt16, att2_w, att2_b, att);
    softmax_n_kernel<<<1, 1024>>>(att, a);

    // 9) pooled = sum_i a_i * emb_i
    colsum_partial<<<NCHUNK, DD>>>(emb, a, part);

    // 10) LN + fc + softmax + argmax
    final_kernel<<<1, DD>>>(part, ln_g, ln_b, fc_w, fc_b, (float*)d_out, out_size);
}